// round 16
// baseline (speedup 1.0000x reference)
#include <cuda_runtime.h>
#include <math.h>

// Problem constants (match reference)
#define NQ   4096     // NUM_Q
#define SQ   256      // MAX_STEP
#define NB   64       // BATCH
#define ROWW (2 * NQ) // 8192 floats per batch row
#define NROWS (NB * (SQ - 1))   // 16320 scanned rows (s=1..255)
#define RPW  4                  // rows per warp
#define NBLK (NROWS / RPW)      // 4080 one-warp blocks

// Scratch (no device allocation allowed)
__device__ int   g_code[NB * SQ];   // per (b,s): (a<<12)|q_idx, or -1 if padded row
__device__ float g_partial[NB];     // per-student loss

// ---------------------------------------------------------------------------
// Phase 1: one warp scans FOUR rows simultaneously.
// Each iteration issues a 2KB super-chunk (4 coalesced 512B segments) for
// every still-active row — up to 8KB / 16 LDG.128 outstanding per warp —
// then resolves each row's ballot independently. Rows early-exit on their
// own, so bytes stay at the ~15.4KB/row optimum while one loaded-DRAM
// latency is amortized over 4 rows' chunks (4x effective MLP vs R8).
// ---------------------------------------------------------------------------
__global__ __launch_bounds__(32) void scan_rows(const float* __restrict__ batch) {
    int lane = threadIdx.x;             // 0..31
    int r0   = blockIdx.x * RPW;        // first of 4 consecutive rows

    const float4* rowp[RPW];
    #pragma unroll
    for (int k = 0; k < RPW; ++k) {
        int r = r0 + k;
        int b = r / (SQ - 1);
        int s = 1 + (r % (SQ - 1));     // row 0 is never used by the reference
        rowp[k] = (const float4*)(batch + (size_t)(b * SQ + s) * ROWW);
    }

    int loc0 = -1, loc1 = -1, loc2 = -1, loc3 = -1;
    int act = 0xF;                      // active-row bitmask (warp-uniform)

    #pragma unroll 1
    for (int c = 0; c < 16 && act; ++c) {
        int base = c * 128 + lane;      // float4 index of segment 0

        // ---- issue phase: all active rows' loads go out back-to-back ----
        float4 a0, a1, a2, a3, b0, b1, b2, b3;
        float4 c0, c1, c2, c3, d0, d1, d2, d3;
        if (act & 1) { a0 = rowp[0][base]; a1 = rowp[0][base+32]; a2 = rowp[0][base+64]; a3 = rowp[0][base+96]; }
        if (act & 2) { b0 = rowp[1][base]; b1 = rowp[1][base+32]; b2 = rowp[1][base+64]; b3 = rowp[1][base+96]; }
        if (act & 4) { c0 = rowp[2][base]; c1 = rowp[2][base+32]; c2 = rowp[2][base+64]; c3 = rowp[2][base+96]; }
        if (act & 8) { d0 = rowp[3][base]; d1 = rowp[3][base+32]; d2 = rowp[3][base+64]; d3 = rowp[3][base+96]; }

        int p0 = base * 4, p1 = (base + 32) * 4, p2 = (base + 64) * 4, p3 = (base + 96) * 4;

        // ---- resolve phase: per-row test + independent ballot exit ----
        if (act & 1) {
            if (a0.x != 0.0f) loc0 = p0+0;  if (a0.y != 0.0f) loc0 = p0+1;
            if (a0.z != 0.0f) loc0 = p0+2;  if (a0.w != 0.0f) loc0 = p0+3;
            if (a1.x != 0.0f) loc0 = p1+0;  if (a1.y != 0.0f) loc0 = p1+1;
            if (a1.z != 0.0f) loc0 = p1+2;  if (a1.w != 0.0f) loc0 = p1+3;
            if (a2.x != 0.0f) loc0 = p2+0;  if (a2.y != 0.0f) loc0 = p2+1;
            if (a2.z != 0.0f) loc0 = p2+2;  if (a2.w != 0.0f) loc0 = p2+3;
            if (a3.x != 0.0f) loc0 = p3+0;  if (a3.y != 0.0f) loc0 = p3+1;
            if (a3.z != 0.0f) loc0 = p3+2;  if (a3.w != 0.0f) loc0 = p3+3;
            if (__ballot_sync(0xffffffffu, loc0 >= 0)) act &= ~1;
        }
        if (act & 2) {
            if (b0.x != 0.0f) loc1 = p0+0;  if (b0.y != 0.0f) loc1 = p0+1;
            if (b0.z != 0.0f) loc1 = p0+2;  if (b0.w != 0.0f) loc1 = p0+3;
            if (b1.x != 0.0f) loc1 = p1+0;  if (b1.y != 0.0f) loc1 = p1+1;
            if (b1.z != 0.0f) loc1 = p1+2;  if (b1.w != 0.0f) loc1 = p1+3;
            if (b2.x != 0.0f) loc1 = p2+0;  if (b2.y != 0.0f) loc1 = p2+1;
            if (b2.z != 0.0f) loc1 = p2+2;  if (b2.w != 0.0f) loc1 = p2+3;
            if (b3.x != 0.0f) loc1 = p3+0;  if (b3.y != 0.0f) loc1 = p3+1;
            if (b3.z != 0.0f) loc1 = p3+2;  if (b3.w != 0.0f) loc1 = p3+3;
            if (__ballot_sync(0xffffffffu, loc1 >= 0)) act &= ~2;
        }
        if (act & 4) {
            if (c0.x != 0.0f) loc2 = p0+0;  if (c0.y != 0.0f) loc2 = p0+1;
            if (c0.z != 0.0f) loc2 = p0+2;  if (c0.w != 0.0f) loc2 = p0+3;
            if (c1.x != 0.0f) loc2 = p1+0;  if (c1.y != 0.0f) loc2 = p1+1;
            if (c1.z != 0.0f) loc2 = p1+2;  if (c1.w != 0.0f) loc2 = p1+3;
            if (c2.x != 0.0f) loc2 = p2+0;  if (c2.y != 0.0f) loc2 = p2+1;
            if (c2.z != 0.0f) loc2 = p2+2;  if (c2.w != 0.0f) loc2 = p2+3;
            if (c3.x != 0.0f) loc2 = p3+0;  if (c3.y != 0.0f) loc2 = p3+1;
            if (c3.z != 0.0f) loc2 = p3+2;  if (c3.w != 0.0f) loc2 = p3+3;
            if (__ballot_sync(0xffffffffu, loc2 >= 0)) act &= ~4;
        }
        if (act & 8) {
            if (d0.x != 0.0f) loc3 = p0+0;  if (d0.y != 0.0f) loc3 = p0+1;
            if (d0.z != 0.0f) loc3 = p0+2;  if (d0.w != 0.0f) loc3 = p0+3;
            if (d1.x != 0.0f) loc3 = p1+0;  if (d1.y != 0.0f) loc3 = p1+1;
            if (d1.z != 0.0f) loc3 = p1+2;  if (d1.w != 0.0f) loc3 = p1+3;
            if (d2.x != 0.0f) loc3 = p2+0;  if (d2.y != 0.0f) loc3 = p2+1;
            if (d2.z != 0.0f) loc3 = p2+2;  if (d2.w != 0.0f) loc3 = p2+3;
            if (d3.x != 0.0f) loc3 = p3+0;  if (d3.y != 0.0f) loc3 = p3+1;
            if (d3.z != 0.0f) loc3 = p3+2;  if (d3.w != 0.0f) loc3 = p3+3;
            if (__ballot_sync(0xffffffffu, loc3 >= 0)) act &= ~8;
        }
    }

    // per-row warp max-reduce + write (at most one lane holds >= 0 per row)
    int locs[RPW] = {loc0, loc1, loc2, loc3};
    #pragma unroll
    for (int k = 0; k < RPW; ++k) {
        int m = locs[k];
        #pragma unroll
        for (int off = 16; off; off >>= 1)
            m = max(m, __shfl_xor_sync(0xffffffffu, m, off));
        if (lane == 0) {
            int code = -1;
            if (m >= 0) {
                int a = (m < NQ) ? 1 : 0;   // first half = answered correctly
                code = (a << 12) | (m & (NQ - 1));
            }
            int r = r0 + k;
            int b = r / (SQ - 1);
            int s = 1 + (r % (SQ - 1));
            g_code[b * SQ + s] = code;
        }
    }
}

// ---------------------------------------------------------------------------
// Phase 2: one block per student. Gather pred, BCE, trim index, per-b loss.
// ---------------------------------------------------------------------------
__global__ __launch_bounds__(256) void per_batch(const float* __restrict__ pred,
                                                 const float* __restrict__ target_q,
                                                 const float* __restrict__ target_label) {
    int b = blockIdx.x;
    int t = threadIdx.x;                 // s index for t < SQ-1

    float bce = 0.0f;
    int   idx = 1 << 20;                 // sentinel for min-reduce
    if (t < SQ - 1) {
        int code = g_code[b * SQ + t + 1];
        if (code >= 0) {
            float p = pred[(size_t)(b * SQ + t) * NQ + (code & (NQ - 1))];
            float a = (float)((code >> 12) & 1);
            float lp  = fmaxf(logf(p),    -100.0f);
            float l1p = fmaxf(log1pf(-p), -100.0f);
            bce = -(a * lp + (1.0f - a) * l1p);
            idx = t;                     // p > 0 guaranteed (pred in (0.01,0.99))
        }
        // padded (code<0): p=0, a=0  ->  BCE == 0, contributes nothing (matches ref)
    }

    // block reduce: sum(bce), min(idx) — fixed tree, deterministic
    #pragma unroll
    for (int off = 16; off; off >>= 1) {
        bce += __shfl_xor_sync(0xffffffffu, bce, off);
        idx  = min(idx, __shfl_xor_sync(0xffffffffu, idx, off));
    }
    __shared__ float ssum[8];
    __shared__ int   smin[8];
    if ((t & 31) == 0) { ssum[t >> 5] = bce; smin[t >> 5] = idx; }
    __syncthreads();
    if (t == 0) {
        float total = ssum[0];
        int   im    = smin[0];
        #pragma unroll
        for (int w = 1; w < 8; ++w) { total += ssum[w]; im = min(im, smin[w]); }
        if (im >= SQ - 1) im = 0;        // argmax of all-False returns 0 (ref semantics)

        float p = target_q[b];           // target_q is [B,1]
        float a = target_label[b];
        float tail = -(a * fmaxf(logf(p), -100.0f) +
                       (1.0f - a) * fmaxf(log1pf(-p), -100.0f));
        float n = (float)(SQ - im);      // (S-1) - i + 1
        g_partial[b] = (total + tail) / n;
    }
}

// ---------------------------------------------------------------------------
// Phase 3: fold 64 partials into the scalar output.
// ---------------------------------------------------------------------------
__global__ void final_sum(float* __restrict__ out) {
    int t = threadIdx.x;                 // 32 threads
    float v = g_partial[t] + g_partial[t + 32];
    #pragma unroll
    for (int off = 16; off; off >>= 1)
        v += __shfl_xor_sync(0xffffffffu, v, off);
    if (t == 0) out[0] = v;
}

// ---------------------------------------------------------------------------
extern "C" void kernel_launch(void* const* d_in, const int* in_sizes, int n_in,
                              void* d_out, int out_size) {
    const float *pred = nullptr, *batch = nullptr, *tq = nullptr, *tl = nullptr;
    for (int i = 0; i < n_in; ++i) {
        long sz = in_sizes[i];
        if (sz == (long)NB * SQ * NQ)          pred  = (const float*)d_in[i];
        else if (sz == (long)NB * SQ * ROWW)   batch = (const float*)d_in[i];
        else if (sz == NB) {                    // dict order: target_q then target_label
            if (!tq) tq = (const float*)d_in[i];
            else     tl = (const float*)d_in[i];
        }
    }

    scan_rows<<<NBLK, 32>>>(batch);
    per_batch<<<NB, 256>>>(pred, tq, tl);
    final_sum<<<1, 32>>>((float*)d_out);
}

// round 17
// speedup vs baseline: 1.0730x; 1.0730x over previous
#include <cuda_runtime.h>
#include <math.h>

// Problem constants (match reference)
#define NQ   4096     // NUM_Q
#define SQ   256      // MAX_STEP
#define NB   64       // BATCH
#define ROWW (2 * NQ) // 8192 floats per batch row
#define NROWS (NB * (SQ - 1))   // 16320 scanned rows (s=1..255)

// Scratch (no device allocation allowed)
__device__ int   g_code[NB * SQ];   // per (b,s): (a<<12)|q_idx, or -1 if padded row
__device__ float g_partial[NB];     // per-student loss

// ---------------------------------------------------------------------------
// Phase 1: 64-thread blocks, TWO independent warps, ONE ROW PER WARP.
// The 32-blocks/SM CTA cap limited R8's 32-thread version to 32 warps/SM
// (64KB in flight < the ~84KB needed to cover loaded DRAM latency at the
// per-SM L2 share). Two warps per block doubles resident warps to 64/SM
// (~100KB effective in flight after the max-of-2 retirement penalty) while
// keeping the cheap 2KB-chunk early-exit pattern (regs ~34, no spills).
// Expected 7.7/16 chunks read => ~15.4KB per 32KB row => ~251MB traffic.
// ---------------------------------------------------------------------------
__global__ __launch_bounds__(64) void scan_rows(const float* __restrict__ batch) {
    int lane = threadIdx.x & 31;
    int w    = threadIdx.x >> 5;        // 0..1
    int r    = blockIdx.x * 2 + w;      // row id 0..NROWS-1
    int b = r / (SQ - 1);
    int s = 1 + (r % (SQ - 1));         // row 0 is never used by the reference
    const float4* row =
        (const float4*)(batch + (size_t)(b * SQ + s) * ROWW);

    int local = -1;                     // float position of nonzero (if in my lanes)
    #pragma unroll 1
    for (int c = 0; c < 16; ++c) {      // 16 x 2KB super-chunks per row
        // 4 independent 512B segments -> 4 outstanding loads per lane
        float4 v0 = row[c * 128 +   0 + lane];
        float4 v1 = row[c * 128 +  32 + lane];
        float4 v2 = row[c * 128 +  64 + lane];
        float4 v3 = row[c * 128 +  96 + lane];

        int b0 = (c * 128 +   0 + lane) * 4;
        int b1 = (c * 128 +  32 + lane) * 4;
        int b2 = (c * 128 +  64 + lane) * 4;
        int b3 = (c * 128 +  96 + lane) * 4;
        if (v0.x != 0.0f) local = b0 + 0;
        if (v0.y != 0.0f) local = b0 + 1;
        if (v0.z != 0.0f) local = b0 + 2;
        if (v0.w != 0.0f) local = b0 + 3;
        if (v1.x != 0.0f) local = b1 + 0;
        if (v1.y != 0.0f) local = b1 + 1;
        if (v1.z != 0.0f) local = b1 + 2;
        if (v1.w != 0.0f) local = b1 + 3;
        if (v2.x != 0.0f) local = b2 + 0;
        if (v2.y != 0.0f) local = b2 + 1;
        if (v2.z != 0.0f) local = b2 + 2;
        if (v2.w != 0.0f) local = b2 + 3;
        if (v3.x != 0.0f) local = b3 + 0;
        if (v3.y != 0.0f) local = b3 + 1;
        if (v3.z != 0.0f) local = b3 + 2;
        if (v3.w != 0.0f) local = b3 + 3;

        if (__ballot_sync(0xffffffffu, local >= 0)) break;  // warp-uniform exit
    }

    // warp max-reduce: at most one lane holds a value >= 0
    #pragma unroll
    for (int off = 16; off; off >>= 1)
        local = max(local, __shfl_xor_sync(0xffffffffu, local, off));

    if (lane == 0) {
        int code = -1;
        if (local >= 0) {
            int a = (local < NQ) ? 1 : 0;   // first half = answered correctly
            code = (a << 12) | (local & (NQ - 1));
        }
        g_code[b * SQ + s] = code;
    }
}

// ---------------------------------------------------------------------------
// Phase 2: one block per student. Gather pred, BCE, trim index, per-b loss.
// ---------------------------------------------------------------------------
__global__ __launch_bounds__(256) void per_batch(const float* __restrict__ pred,
                                                 const float* __restrict__ target_q,
                                                 const float* __restrict__ target_label) {
    int b = blockIdx.x;
    int t = threadIdx.x;                 // s index for t < SQ-1

    float bce = 0.0f;
    int   idx = 1 << 20;                 // sentinel for min-reduce
    if (t < SQ - 1) {
        int code = g_code[b * SQ + t + 1];
        if (code >= 0) {
            float p = pred[(size_t)(b * SQ + t) * NQ + (code & (NQ - 1))];
            float a = (float)((code >> 12) & 1);
            float lp  = fmaxf(logf(p),    -100.0f);
            float l1p = fmaxf(log1pf(-p), -100.0f);
            bce = -(a * lp + (1.0f - a) * l1p);
            idx = t;                     // p > 0 guaranteed (pred in (0.01,0.99))
        }
        // padded (code<0): p=0, a=0  ->  BCE == 0, contributes nothing (matches ref)
    }

    // block reduce: sum(bce), min(idx) — fixed tree, deterministic
    #pragma unroll
    for (int off = 16; off; off >>= 1) {
        bce += __shfl_xor_sync(0xffffffffu, bce, off);
        idx  = min(idx, __shfl_xor_sync(0xffffffffu, idx, off));
    }
    __shared__ float ssum[8];
    __shared__ int   smin[8];
    if ((t & 31) == 0) { ssum[t >> 5] = bce; smin[t >> 5] = idx; }
    __syncthreads();
    if (t == 0) {
        float total = ssum[0];
        int   im    = smin[0];
        #pragma unroll
        for (int w = 1; w < 8; ++w) { total += ssum[w]; im = min(im, smin[w]); }
        if (im >= SQ - 1) im = 0;        // argmax of all-False returns 0 (ref semantics)

        float p = target_q[b];           // target_q is [B,1]
        float a = target_label[b];
        float tail = -(a * fmaxf(logf(p), -100.0f) +
                       (1.0f - a) * fmaxf(log1pf(-p), -100.0f));
        float n = (float)(SQ - im);      // (S-1) - i + 1
        g_partial[b] = (total + tail) / n;
    }
}

// ---------------------------------------------------------------------------
// Phase 3: fold 64 partials into the scalar output.
// ---------------------------------------------------------------------------
__global__ void final_sum(float* __restrict__ out) {
    int t = threadIdx.x;                 // 32 threads
    float v = g_partial[t] + g_partial[t + 32];
    #pragma unroll
    for (int off = 16; off; off >>= 1)
        v += __shfl_xor_sync(0xffffffffu, v, off);
    if (t == 0) out[0] = v;
}

// ---------------------------------------------------------------------------
extern "C" void kernel_launch(void* const* d_in, const int* in_sizes, int n_in,
                              void* d_out, int out_size) {
    const float *pred = nullptr, *batch = nullptr, *tq = nullptr, *tl = nullptr;
    for (int i = 0; i < n_in; ++i) {
        long sz = in_sizes[i];
        if (sz == (long)NB * SQ * NQ)          pred  = (const float*)d_in[i];
        else if (sz == (long)NB * SQ * ROWW)   batch = (const float*)d_in[i];
        else if (sz == NB) {                    // dict order: target_q then target_label
            if (!tq) tq = (const float*)d_in[i];
            else     tl = (const float*)d_in[i];
        }
    }

    scan_rows<<<NROWS / 2, 64>>>(batch);
    per_batch<<<NB, 256>>>(pred, tq, tl);
    final_sum<<<1, 32>>>((float*)d_out);
}